// round 8
// baseline (speedup 1.0000x reference)
#include <cuda_runtime.h>
#include <cuda_bf16.h>
#include <cstdint>

#define N_NODES 100000
#define N_EDGES 320000
#define DIM 256

#define SCAN_B 256
#define NBLK ((N_NODES + SCAN_B - 1) / SCAN_B)

// ---------------- scratch (no allocations allowed) ----------------
__device__ int   g_deg_out[N_NODES];
__device__ int   g_deg_in[N_NODES];
__device__ float g_inv_out[N_NODES];
__device__ float g_inv_in[N_NODES];
__device__ float g_h[(size_t)N_NODES * DIM];
// CSR (by dst)
__device__ int g_off[N_NODES + 1];
__device__ int g_cur[N_NODES];
__device__ int g_part[NBLK];
__device__ int g_esrc[N_EDGES];
// W transposed to [N,K], bf16 hi/lo
__device__ __nv_bfloat16 g_bt1_hi[DIM * DIM];
__device__ __nv_bfloat16 g_bt1_lo[DIM * DIM];
__device__ __nv_bfloat16 g_bt2_hi[DIM * DIM];
__device__ __nv_bfloat16 g_bt2_lo[DIM * DIM];

// ---------------- helpers ----------------
__device__ __forceinline__ uint32_t smem_u32(const void* p) {
    uint32_t a;
    asm("{ .reg .u64 t; cvta.to.shared.u64 t, %1; cvt.u32.u64 %0, t; }" : "=r"(a) : "l"(p));
    return a;
}
__device__ __forceinline__ void cp16(uint32_t dst, const void* src) {
    asm volatile("cp.async.cg.shared.global [%0], [%1], 16;"
                 :: "r"(dst), "l"(src) : "memory");
}
__device__ __forceinline__ void cp_commit() {
    asm volatile("cp.async.commit_group;" ::: "memory");
}
__device__ __forceinline__ void cp_wait0() {
    asm volatile("cp.async.wait_group 0;" ::: "memory");
}
__device__ __forceinline__ void cp_wait1() {
    asm volatile("cp.async.wait_group 1;" ::: "memory");
}
__device__ __forceinline__ void ldm4(uint32_t* r, uint32_t addr) {
    asm volatile("ldmatrix.sync.aligned.m8n8.x4.shared.b16 {%0,%1,%2,%3}, [%4];"
                 : "=r"(r[0]), "=r"(r[1]), "=r"(r[2]), "=r"(r[3]) : "r"(addr));
}
__device__ __forceinline__ void mma16816(float* c, const uint32_t* a, uint32_t b0, uint32_t b1) {
    asm volatile("mma.sync.aligned.m16n8k16.row.col.f32.bf16.bf16.f32 "
                 "{%0,%1,%2,%3}, {%4,%5,%6,%7}, {%8,%9}, {%0,%1,%2,%3};"
                 : "+f"(c[0]), "+f"(c[1]), "+f"(c[2]), "+f"(c[3])
                 : "r"(a[0]), "r"(a[1]), "r"(a[2]), "r"(a[3]), "r"(b0), "r"(b1));
}
__device__ __forceinline__ uint32_t pack_hi(float x, float y) {
    return (uint32_t)__bfloat16_as_ushort(__float2bfloat16(x)) |
           ((uint32_t)__bfloat16_as_ushort(__float2bfloat16(y)) << 16);
}
__device__ __forceinline__ uint32_t pack_lo(float x, float y) {
    float rx = x - __bfloat162float(__float2bfloat16(x));
    float ry = y - __bfloat162float(__float2bfloat16(y));
    return (uint32_t)__bfloat16_as_ushort(__float2bfloat16(rx)) |
           ((uint32_t)__bfloat16_as_ushort(__float2bfloat16(ry)) << 16);
}
__device__ __forceinline__ void fma4(float4& a, float w, const float4& v) {
    a.x = fmaf(w, v.x, a.x); a.y = fmaf(w, v.y, a.y);
    a.z = fmaf(w, v.z, a.z); a.w = fmaf(w, v.w, a.w);
}
__device__ __forceinline__ void sts_u2(uint32_t addr, uint2 v) {
    asm volatile("st.shared.v2.u32 [%0], {%1, %2};" :: "r"(addr), "r"(v.x), "r"(v.y) : "memory");
}

// ---------------- graph prep ----------------
__global__ void k_init_counts() {
    int i = blockIdx.x * blockDim.x + threadIdx.x;
    if (i < N_NODES) { g_deg_out[i] = 0; g_deg_in[i] = 0; }
}
__global__ void k_count_deg(const int* __restrict__ src, const int* __restrict__ dst) {
    int e = blockIdx.x * blockDim.x + threadIdx.x;
    if (e < N_EDGES) {
        atomicAdd(&g_deg_out[src[e]], 1);
        atomicAdd(&g_deg_in[dst[e]], 1);
    }
}
__global__ void k_scan1() {
    __shared__ int sh[SCAN_B];
    int i = blockIdx.x * SCAN_B + threadIdx.x;
    int v = (i < N_NODES) ? g_deg_in[i] : 0;
    sh[threadIdx.x] = v;
    __syncthreads();
#pragma unroll
    for (int o = 1; o < SCAN_B; o <<= 1) {
        int t = (threadIdx.x >= o) ? sh[threadIdx.x - o] : 0;
        __syncthreads();
        sh[threadIdx.x] += t;
        __syncthreads();
    }
    if (i < N_NODES) g_off[i] = sh[threadIdx.x] - v;
    if (threadIdx.x == SCAN_B - 1) g_part[blockIdx.x] = sh[SCAN_B - 1];
}
__global__ void k_scan2() {
    __shared__ int sh[512];
    int t = threadIdx.x;
    int v = (t < NBLK) ? g_part[t] : 0;
    sh[t] = v;
    __syncthreads();
#pragma unroll
    for (int o = 1; o < 512; o <<= 1) {
        int x = (t >= o) ? sh[t - o] : 0;
        __syncthreads();
        sh[t] += x;
        __syncthreads();
    }
    if (t < NBLK) g_part[t] = sh[t] - v;
}
__global__ void k_scan3_inv() {
    int i = blockIdx.x * SCAN_B + threadIdx.x;
    if (i < N_NODES) {
        int o = g_off[i] + g_part[blockIdx.x];
        g_off[i] = o;
        g_cur[i] = o;
        g_inv_out[i] = rsqrtf(fmaxf((float)g_deg_out[i], 1.0f));
        g_inv_in[i]  = rsqrtf(fmaxf((float)g_deg_in[i], 1.0f));
    }
    if (i == 0) g_off[N_NODES] = N_EDGES;
}
__global__ void k_bucket(const int* __restrict__ src, const int* __restrict__ dst) {
    int e = blockIdx.x * blockDim.x + threadIdx.x;
    if (e < N_EDGES) {
        int p = atomicAdd(&g_cur[dst[e]], 1);
        g_esrc[p] = src[e];
    }
}
__global__ void k_prep_w2(const float* __restrict__ W1, const float* __restrict__ W2) {
    int i = blockIdx.x * blockDim.x + threadIdx.x;
    int layer = i >= DIM * DIM;
    int j = i - layer * DIM * DIM;
    if (i >= 2 * DIM * DIM) return;
    int n = j >> 8, k = j & 255;
    float v = layer ? W2[k * DIM + n] : W1[k * DIM + n];
    __nv_bfloat16 h = __float2bfloat16(v);
    float l = v - __bfloat162float(h);
    if (layer) { g_bt2_hi[j] = h; g_bt2_lo[j] = __float2bfloat16(l); }
    else       { g_bt1_hi[j] = h; g_bt1_lo[j] = __float2bfloat16(l); }
}

// ---------------- fused gather + GEMM ----------------
// SMEM: A hi [4 chunks x 16KB] = 64K, A lo +64K  (128 rows x 256 K, swizzled per chunk)
//       B: 2 stages x (hi 20K + lo 20K), 80B row stride (conflict-free), at +128K
// Total 208 KB.
#define OFF_ALO  65536
#define OFF_BB   131072
#define BSTG     40960
#define BTERM    20480
#define SMEM_TOT 212992

__global__ __launch_bounds__(512, 1)
void k_fused(const float* __restrict__ feat,
             const __nv_bfloat16* __restrict__ Bh_g,
             const __nv_bfloat16* __restrict__ Bl_g,
             const float* __restrict__ bias, float* __restrict__ out) {
    extern __shared__ char smem[];
    const uint32_t sb = smem_u32(smem);
    const int tid = threadIdx.x, lane = tid & 31, wid = tid >> 5;
    const int wm = wid >> 3, wn = wid & 7;
    const int row0 = blockIdx.x * 128;

    // B chunk prefetch: chunk c = K cols [c*32, c*32+32), stage s.
#define CPB32(s, c)                                                                  \
    {                                                                                \
        _Pragma("unroll")                                                            \
        for (int it = 0; it < 4; it++) {                                             \
            int id = tid + it * 512;                 /* 0..2047 */                   \
            int term = id >> 10;                     /* 0=hi 1=lo */                 \
            int n = (id >> 2) & 255, kc = id & 3;                                    \
            uint32_t dst = sb + OFF_BB + (s) * BSTG + term * BTERM + n * 80 + kc * 16; \
            const __nv_bfloat16* srcp = (term ? Bl_g : Bh_g) + n * DIM + (c) * 32 + kc * 8; \
            cp16(dst, srcp);                                                         \
        }                                                                            \
        cp_commit();                                                                 \
    }

    // kick off B chunks 0 and 1 before gather (independent of gather)
    CPB32(0, 0);
    CPB32(1, 1);

    // ---------- phase 1: gather 8 nodes per warp into resident A SMEM ----------
    {
        // A store address pieces for this lane (cols 4*lane and 4*lane+128)
        const int pcu = (lane & 15) >> 1;          // 16B unit within 64-col chunk
        const int subo = (lane & 1) * 8;           // 8B half
        const int ca0 = lane >> 4;                 // chunk 0/1
        for (int i = 0; i < 8; i++) {
            int r = wid * 8 + i;                   // CTA-local row
            int node = row0 + r;
            float4 a0 = make_float4(0.f, 0.f, 0.f, 0.f);
            float4 a1 = a0;
            if (node < N_NODES) {
                int e = g_off[node], e1 = g_off[node + 1];
                for (; e + 2 <= e1; e += 2) {
                    int   sA = g_esrc[e], sB2 = g_esrc[e + 1];
                    float wA = g_inv_out[sA], wB = g_inv_out[sB2];
                    const float4* fA = (const float4*)(feat + (size_t)sA * DIM);
                    const float4* fB = (const float4*)(feat + (size_t)sB2 * DIM);
                    float4 vA0 = fA[lane], vA1 = fA[lane + 32];
                    float4 vB0 = fB[lane], vB1 = fB[lane + 32];
                    fma4(a0, wA, vA0); fma4(a1, wA, vA1);
                    fma4(a0, wB, vB0); fma4(a1, wB, vB1);
                }
                if (e < e1) {
                    int s2 = g_esrc[e];
                    float w = g_inv_out[s2];
                    const float4* fr = (const float4*)(feat + (size_t)s2 * DIM);
                    float4 v0 = fr[lane], v1 = fr[lane + 32];
                    fma4(a0, w, v0); fma4(a1, w, v1);
                }
            }
            uint32_t base = sb + r * 128 + ((pcu ^ (r & 7)) << 4) + subo;
            sts_u2(base + ca0 * 16384,
                   make_uint2(pack_hi(a0.x, a0.y), pack_hi(a0.z, a0.w)));
            sts_u2(base + ca0 * 16384 + OFF_ALO,
                   make_uint2(pack_lo(a0.x, a0.y), pack_lo(a0.z, a0.w)));
            sts_u2(base + (2 + ca0) * 16384,
                   make_uint2(pack_hi(a1.x, a1.y), pack_hi(a1.z, a1.w)));
            sts_u2(base + (2 + ca0) * 16384 + OFF_ALO,
                   make_uint2(pack_lo(a1.x, a1.y), pack_lo(a1.z, a1.w)));
        }
    }

    // ---------- phase 2: GEMM ----------
    float acc[4][4][4];
#pragma unroll
    for (int i = 0; i < 4; i++)
#pragma unroll
        for (int j = 0; j < 4; j++)
#pragma unroll
            for (int k = 0; k < 4; k++) acc[i][j][k] = 0.f;

#pragma unroll
    for (int c = 0; c < 8; c++) {                  // 8 B-chunks of K=32
        if (c == 7) cp_wait0(); else cp_wait1();
        __syncthreads();                            // also joins gather on c==0

        const uint32_t stb = sb + OFF_BB + (c & 1) * BSTG;
#pragma unroll
        for (int kb = 0; kb < 2; kb++) {           // two k16 steps per chunk
            const int g = c * 2 + kb;
            const int cA = g >> 2, kA = g & 3;
            const uint32_t sta = sb + cA * 16384;

            uint32_t ah[4][4], al[4][4];
#pragma unroll
            for (int fm = 0; fm < 4; fm++) {
                int row = wm * 64 + fm * 16 + (lane & 15);
                int kc = kA * 2 + (lane >> 4);
                uint32_t a = sta + row * 128 + ((kc ^ (row & 7)) << 4);
                ldm4(ah[fm], a);
                ldm4(al[fm], a + OFF_ALO);
            }
            uint32_t bh[2][4], bl[2][4];
#pragma unroll
            for (int rg = 0; rg < 2; rg++) {
                int nrow = wn * 32 + rg * 16 + (lane & 7) + ((lane & 16) >> 1);
                int kc = kb * 2 + ((lane >> 3) & 1);
                uint32_t a = stb + nrow * 80 + kc * 16;
                ldm4(bh[rg], a);
                ldm4(bl[rg], a + BTERM);
            }
#pragma unroll
            for (int fm = 0; fm < 4; fm++)
#pragma unroll
                for (int fn = 0; fn < 4; fn++) {
                    int rg = fn >> 1, o = (fn & 1) * 2;
                    mma16816(acc[fm][fn], ah[fm], bh[rg][o], bh[rg][o + 1]);
                    mma16816(acc[fm][fn], ah[fm], bl[rg][o], bl[rg][o + 1]);
                    mma16816(acc[fm][fn], al[fm], bh[rg][o], bh[rg][o + 1]);
                }
        }
        __syncthreads();
        if (c < 6) CPB32(c & 1, c + 2);
    }

    // ---------- epilogue: dst-norm + bias + relu ----------
#pragma unroll
    for (int fm = 0; fm < 4; fm++) {
        int mbase = row0 + wm * 64 + fm * 16 + (lane >> 2);
#pragma unroll
        for (int half = 0; half < 2; half++) {
            int row = mbase + half * 8;
            if (row >= N_NODES) continue;
            float sc = g_inv_in[row];
#pragma unroll
            for (int fn = 0; fn < 4; fn++) {
                int col = wn * 32 + fn * 8 + 2 * (lane & 3);
                float v0 = acc[fm][fn][half * 2 + 0];
                float v1 = acc[fm][fn][half * 2 + 1];
                float2 o;
                o.x = fmaxf(fmaf(v0, sc, bias[col]), 0.f);
                o.y = fmaxf(fmaf(v1, sc, bias[col + 1]), 0.f);
                *(float2*)(out + (size_t)row * DIM + col) = o;
            }
        }
    }
}

// ---------------- launch ----------------
extern "C" void kernel_launch(void* const* d_in, const int* in_sizes, int n_in,
                              void* d_out, int out_size) {
    const int*   src  = (const int*)d_in[0];
    const int*   dst  = (const int*)d_in[1];
    const float* feat = (const float*)d_in[2];
    const float* W1   = (const float*)d_in[3];
    const float* b1   = (const float*)d_in[4];
    const float* W2   = (const float*)d_in[5];
    const float* b2   = (const float*)d_in[6];
    float*       out  = (float*)d_out;

    float* h; cudaGetSymbolAddress((void**)&h, g_h);
    __nv_bfloat16 *bt1h, *bt1l, *bt2h, *bt2l;
    cudaGetSymbolAddress((void**)&bt1h, g_bt1_hi);
    cudaGetSymbolAddress((void**)&bt1l, g_bt1_lo);
    cudaGetSymbolAddress((void**)&bt2h, g_bt2_hi);
    cudaGetSymbolAddress((void**)&bt2l, g_bt2_lo);

    static int smem_set = 0;
    if (!smem_set) {
        cudaFuncSetAttribute(k_fused, cudaFuncAttributeMaxDynamicSharedMemorySize, SMEM_TOT);
        smem_set = 1;
    }

    const int T = 256;
    const int grid = (N_NODES + 127) / 128;

    // ---- prep ----
    k_init_counts<<<(N_NODES + T - 1) / T, T>>>();
    k_count_deg<<<(N_EDGES + T - 1) / T, T>>>(src, dst);
    k_scan1<<<NBLK, SCAN_B>>>();
    k_scan2<<<1, 512>>>();
    k_scan3_inv<<<NBLK, SCAN_B>>>();
    k_bucket<<<(N_EDGES + T - 1) / T, T>>>(src, dst);
    k_prep_w2<<<(2 * DIM * DIM + T - 1) / T, T>>>(W1, W2);

    // ---- layer 1 / layer 2 ----
    k_fused<<<grid, 512, SMEM_TOT>>>(feat, bt1h, bt1l, b1, h);
    k_fused<<<grid, 512, SMEM_TOT>>>(h,    bt2h, bt2l, b2, out);
}